// round 5
// baseline (speedup 1.0000x reference)
#include <cuda_runtime.h>
#include <math.h>

#define L 2048
#define H 512
#define NSTATE 32
#define NL 4
#define INDIM 4
#define OUTDIM 3

#define NCHUNK 16
#define CLEN 128   // L / NCHUNK

// Scratch (allocation-free rule: device globals)
__device__ float g_h[L * H];   // residual stream
__device__ float g_u[L * H];   // layernorm output
__device__ float g_y[L * H];   // gelu(scan output)

// ---------------------------------------------------------------------------
// Encoder
// ---------------------------------------------------------------------------
__global__ void enc_kernel(const float* __restrict__ x,
                           const float* __restrict__ w,
                           const float* __restrict__ b) {
    int t = blockIdx.x;
    int j = threadIdx.x;
    float4 xr = *(const float4*)(x + t * INDIM);
    float4 wr = *(const float4*)(w + j * INDIM);
    g_h[t * H + j] = b[j] + xr.x * wr.x + xr.y * wr.y + xr.z * wr.z + xr.w * wr.w;
}

// ---------------------------------------------------------------------------
// LayerNorm over H=512 per row
// ---------------------------------------------------------------------------
__global__ void ln_kernel(const float* __restrict__ nw,
                          const float* __restrict__ nb) {
    int t = blockIdx.x;
    int tid = threadIdx.x;
    float v0 = g_h[t * H + tid];
    float v1 = g_h[t * H + tid + 256];
    float s = v0 + v1;
    float sq = v0 * v0 + v1 * v1;
#pragma unroll
    for (int off = 16; off; off >>= 1) {
        s  += __shfl_xor_sync(0xffffffffu, s, off);
        sq += __shfl_xor_sync(0xffffffffu, sq, off);
    }
    __shared__ float ss[8], ssq[8];
    int w = tid >> 5;
    if ((tid & 31) == 0) { ss[w] = s; ssq[w] = sq; }
    __syncthreads();
    __shared__ float m_sh, r_sh;
    if (tid == 0) {
        float S = 0.f, Q = 0.f;
#pragma unroll
        for (int i = 0; i < 8; i++) { S += ss[i]; Q += ssq[i]; }
        float m = S * (1.0f / H);
        float var = Q * (1.0f / H) - m * m;
        m_sh = m;
        r_sh = rsqrtf(var + 1e-5f);
    }
    __syncthreads();
    float m = m_sh, r = r_sh;
    g_u[t * H + tid]       = (v0 - m) * r * nw[tid]       + nb[tid];
    g_u[t * H + tid + 256] = (v1 - m) * r * nw[tid + 256] + nb[tid + 256];
}

// ---------------------------------------------------------------------------
// Discretization coefficients per (channel, lane=state)
// ---------------------------------------------------------------------------
struct SSMCoef { float are, aim, bbr, bbi, cre, cim, dv; };

__device__ __forceinline__ SSMCoef load_coef(
    const float* lre_, const float* lim_, const float* bre_, const float* bim_,
    const float* cre_, const float* cim_, const float* dvec, const float* lstep_,
    int ch, int lane)
{
    int idx = ch * NSTATE + lane;
    float lre = lre_[idx], lim = lim_[idx];
    float step = __expf(lstep_[ch]);
    float s2 = 0.5f * step;
    float dr = 1.f - s2 * lre, di = -s2 * lim;
    float inv = 1.f / (dr * dr + di * di);
    float blr = dr * inv, bli = -di * inv;
    float nr = 1.f + s2 * lre, ni = s2 * lim;
    SSMCoef c;
    c.are = blr * nr - bli * ni;
    c.aim = blr * ni + bli * nr;
    float br = bre_[idx], bi = bim_[idx];
    c.bbr = step * (blr * br - bli * bi);
    c.bbi = step * (blr * bi + bli * br);
    c.cre = cre_[idx];
    c.cim = cim_[idx];
    c.dv = dvec[ch];
    return c;
}

__device__ __forceinline__ float gelu_tanh(float yv) {
    float z = 0.7978845608028654f * fmaf(0.044715f * yv, yv * yv, yv);
    z = fminf(fmaxf(z, -15.f), 15.f);
    float e = __expf(2.f * z);
    float th = (e - 1.f) / (e + 1.f);
    return 0.5f * yv * (1.f + th);
}

// Merge-reduce helpers
__device__ __forceinline__ float merge2(float a, float b, int off, int lane) {
    float t = (lane & off) ? a : b;
    t = __shfl_xor_sync(0xffffffffu, t, off);
    return ((lane & off) ? b : a) + t;
}

__device__ __forceinline__ float reduce8(const float* acc, int lane) {
    float m01 = merge2(acc[0], acc[1], 16, lane);
    float m23 = merge2(acc[2], acc[3], 16, lane);
    float m45 = merge2(acc[4], acc[5], 16, lane);
    float m67 = merge2(acc[6], acc[7], 16, lane);
    float n0  = merge2(m01, m23, 8, lane);
    float n1  = merge2(m45, m67, 8, lane);
    float p   = merge2(n0, n1, 4, lane);
    p += __shfl_xor_sync(0xffffffffu, p, 2);
    p += __shfl_xor_sync(0xffffffffu, p, 1);
    return p;
}

// ---------------------------------------------------------------------------
// Fused scan: one block per channel (512 threads = 16 warps, warp = chunk).
// ---------------------------------------------------------------------------
__global__ __launch_bounds__(512) void scan_fused_kernel(
        const float* __restrict__ lre_, const float* __restrict__ lim_,
        const float* __restrict__ bre_, const float* __restrict__ bim_,
        const float* __restrict__ cre_, const float* __restrict__ cim_,
        const float* __restrict__ dvec, const float* __restrict__ lstep_) {
    __shared__ float2 st[NCHUNK][NSTATE];

    int ch = blockIdx.x;
    int wid = threadIdx.x >> 5;      // chunk
    int lane = threadIdx.x & 31;     // state

    SSMCoef cf = load_coef(lre_, lim_, bre_, bim_, cre_, cim_, dvec, lstep_, ch, lane);
    int myk = ((lane >> 4) & 1) | (((lane >> 3) & 1) << 1) | (((lane >> 2) & 1) << 2);

    int tbase = wid * CLEN;
    const float* up = g_u + ch;
    float* yp = g_y + ch;

    float yreg[16];
    float sre = 0.f, sim = 0.f;

    // ---- Phase A: local scan ----
#pragma unroll
    for (int b = 0; b < 16; b++) {
        int t0 = tbase + b * 8;
        float acc[8], uk[8];
#pragma unroll
        for (int k = 0; k < 8; k++) {
            float u = __ldg(up + (t0 + k) * H);
            float t1 = fmaf(cf.bbr, u, fmaf(-cf.aim, sim, cf.are * sre));
            float t2 = fmaf(cf.bbi, u, fmaf(cf.aim, sre, cf.are * sim));
            sre = t1; sim = t2;
            acc[k] = fmaf(-cf.cim, sim, cf.cre * sre);
            uk[k] = u;
        }
        float red = reduce8(acc, lane);
        float s01 = (lane & 16) ? uk[1] : uk[0];
        float s23 = (lane & 16) ? uk[3] : uk[2];
        float s45 = (lane & 16) ? uk[5] : uk[4];
        float s67 = (lane & 16) ? uk[7] : uk[6];
        float t0s = (lane & 8) ? s23 : s01;
        float t1s = (lane & 8) ? s67 : s45;
        float usel = (lane & 4) ? t1s : t0s;
        yreg[b] = fmaf(cf.dv, usel, 2.f * red);
    }
    st[wid][lane] = make_float2(sre, sim);
    __syncthreads();

    // ---- Phase B: sequential chunk combine (warp 0) ----
    if (wid == 0) {
        float pr = cf.are, pi = cf.aim;
#pragma unroll
        for (int i = 0; i < 7; i++) {   // A^128
            float nr = pr * pr - pi * pi;
            float ni = 2.f * pr * pi;
            pr = nr; pi = ni;
        }
        float cr = 0.f, ci = 0.f;
#pragma unroll
        for (int c = 0; c < NCHUNK; c++) {
            float2 f = st[c][lane];
            st[c][lane] = make_float2(cr, ci);
            float nr = fmaf(pr, cr, fmaf(-pi, ci, f.x));
            float ni = fmaf(pr, ci, fmaf(pi, cr, f.y));
            cr = nr; ci = ni;
        }
    }
    __syncthreads();

    // ---- Phase C: correction + gelu + store ----
    float2 si = st[wid][lane];
    float er = cf.cre * si.x - cf.cim * si.y;
    float ei = cf.cre * si.y + cf.cim * si.x;
    float wr = 1.f, wi = 0.f;

#pragma unroll
    for (int b = 0; b < 16; b++) {
        float acc[8];
#pragma unroll
        for (int k = 0; k < 8; k++) {
            float nr = cf.are * wr - cf.aim * wi;
            float ni = cf.are * wi + cf.aim * wr;
            wr = nr; wi = ni;
            acc[k] = er * wr - ei * wi;
        }
        float corr = reduce8(acc, lane);
        float yv = yreg[b] + 2.f * corr;
        if ((lane & 3) == 0)
            yp[(tbase + b * 8 + myk) * H] = gelu_tanh(yv);
    }
}

// ---------------------------------------------------------------------------
// Fused dual GEMM + gate + residual. BM=32, BN=32, BK=32, 128 threads,
// 1024 blocks (grid-limited occupancy fix), double-buffered smem.
// ---------------------------------------------------------------------------
#define BM 32
#define BN 32
#define BK 32
#define TPAD 36
#define NKIT (H / BK)

__global__ __launch_bounds__(128) void gemm_kernel(const float* __restrict__ W1,
                                                   const float* __restrict__ b1,
                                                   const float* __restrict__ W2,
                                                   const float* __restrict__ b2) {
    __shared__ float As[2][BK][TPAD];    // [k][m]
    __shared__ float B1s[2][BK][TPAD];   // [k][n]
    __shared__ float B2s[2][BK][TPAD];

    int tid = threadIdx.x;
    int tx = tid & 15;        // n: 16 * 2 = 32
    int ty = tid >> 4;        // m: 8 * 4 = 32
    int n0 = blockIdx.x * BN;
    int m0 = blockIdx.y * BM;

    float acc1[4][2] = {};
    float acc2[4][2] = {};

    int ra = tid >> 3;        // rows 0..15 (+16)
    int kk = tid & 7;         // float4 index along k

    // prologue: stage 0
#pragma unroll
    for (int i = 0; i < 2; i++) {
        int r = ra + i * 16;
        float4 va = *(const float4*)&g_y[(m0 + r) * H + kk * 4];
        float4 v1 = *(const float4*)&W1[(n0 + r) * H + kk * 4];
        float4 v2 = *(const float4*)&W2[(n0 + r) * H + kk * 4];
        As[0][kk * 4 + 0][r] = va.x; As[0][kk * 4 + 1][r] = va.y;
        As[0][kk * 4 + 2][r] = va.z; As[0][kk * 4 + 3][r] = va.w;
        B1s[0][kk * 4 + 0][r] = v1.x; B1s[0][kk * 4 + 1][r] = v1.y;
        B1s[0][kk * 4 + 2][r] = v1.z; B1s[0][kk * 4 + 3][r] = v1.w;
        B2s[0][kk * 4 + 0][r] = v2.x; B2s[0][kk * 4 + 1][r] = v2.y;
        B2s[0][kk * 4 + 2][r] = v2.z; B2s[0][kk * 4 + 3][r] = v2.w;
    }
    __syncthreads();

    for (int it = 0; it < NKIT; it++) {
        int cur = it & 1;
        int nxt = cur ^ 1;

        float4 pa[2], pb1[2], pb2[2];
        if (it + 1 < NKIT) {
            int k0n = (it + 1) * BK;
#pragma unroll
            for (int i = 0; i < 2; i++) {
                int r = ra + i * 16;
                pa[i]  = *(const float4*)&g_y[(m0 + r) * H + k0n + kk * 4];
                pb1[i] = *(const float4*)&W1[(n0 + r) * H + k0n + kk * 4];
                pb2[i] = *(const float4*)&W2[(n0 + r) * H + k0n + kk * 4];
            }
        }

#pragma unroll
        for (int k = 0; k < BK; k++) {
            float4 a4 = *(const float4*)&As[cur][k][ty * 4];
            float2 c1 = *(const float2*)&B1s[cur][k][tx * 2];
            float2 c2 = *(const float2*)&B2s[cur][k][tx * 2];
            float av[4] = {a4.x, a4.y, a4.z, a4.w};
#pragma unroll
            for (int i = 0; i < 4; i++) {
                acc1[i][0] = fmaf(av[i], c1.x, acc1[i][0]);
                acc1[i][1] = fmaf(av[i], c1.y, acc1[i][1]);
                acc2[i][0] = fmaf(av[i], c2.x, acc2[i][0]);
                acc2[i][1] = fmaf(av[i], c2.y, acc2[i][1]);
            }
        }

        if (it + 1 < NKIT) {
#pragma unroll
            for (int i = 0; i < 2; i++) {
                int r = ra + i * 16;
                As[nxt][kk * 4 + 0][r] = pa[i].x; As[nxt][kk * 4 + 1][r] = pa[i].y;
                As[nxt][kk * 4 + 2][r] = pa[i].z; As[nxt][kk * 4 + 3][r] = pa[i].w;
                B1s[nxt][kk * 4 + 0][r] = pb1[i].x; B1s[nxt][kk * 4 + 1][r] = pb1[i].y;
                B1s[nxt][kk * 4 + 2][r] = pb1[i].z; B1s[nxt][kk * 4 + 3][r] = pb1[i].w;
                B2s[nxt][kk * 4 + 0][r] = pb2[i].x; B2s[nxt][kk * 4 + 1][r] = pb2[i].y;
                B2s[nxt][kk * 4 + 2][r] = pb2[i].z; B2s[nxt][kk * 4 + 3][r] = pb2[i].w;
            }
            __syncthreads();
        }
    }

#pragma unroll
    for (int i = 0; i < 4; i++) {
        int m = m0 + ty * 4 + i;
#pragma unroll
        for (int j = 0; j < 2; j++) {
            int n = n0 + tx * 2 + j;
            float gg1 = acc1[i][j] + b1[n];
            float gg2 = acc2[i][j] + b2[n];
            float sig = 1.f / (1.f + __expf(-gg2));
            g_h[m * H + n] += gg1 * sig;
        }
    }
}

// ---------------------------------------------------------------------------
// Decoder
// ---------------------------------------------------------------------------
__global__ void dec_kernel(const float* __restrict__ w,
                           const float* __restrict__ b,
                           float* __restrict__ out) {
    int warp = (blockIdx.x * blockDim.x + threadIdx.x) >> 5;
    int lane = threadIdx.x & 31;
    if (warp >= L) return;
    float a0 = 0.f, a1 = 0.f, a2 = 0.f;
#pragma unroll
    for (int j = lane; j < H; j += 32) {
        float hv = g_h[warp * H + j];
        a0 = fmaf(hv, w[j],         a0);
        a1 = fmaf(hv, w[H + j],     a1);
        a2 = fmaf(hv, w[2 * H + j], a2);
    }
#pragma unroll
    for (int off = 16; off; off >>= 1) {
        a0 += __shfl_xor_sync(0xffffffffu, a0, off);
        a1 += __shfl_xor_sync(0xffffffffu, a1, off);
        a2 += __shfl_xor_sync(0xffffffffu, a2, off);
    }
    if (lane == 0) {
        out[warp * 3 + 0] = a0 + b[0];
        out[warp * 3 + 1] = a1 + b[1];
        out[warp * 3 + 2] = a2 + b[2];
    }
}

// ---------------------------------------------------------------------------
extern "C" void kernel_launch(void* const* d_in, const int* in_sizes, int n_in,
                              void* d_out, int out_size) {
    const float* x       = (const float*)d_in[0];
    const float* enc_w   = (const float*)d_in[1];
    const float* enc_b   = (const float*)d_in[2];
    const float* dec_w   = (const float*)d_in[3];
    const float* dec_b   = (const float*)d_in[4];
    const float* norm_w  = (const float*)d_in[5];
    const float* norm_b  = (const float*)d_in[6];
    const float* lam_re  = (const float*)d_in[7];
    const float* lam_im  = (const float*)d_in[8];
    const float* b_re    = (const float*)d_in[9];
    const float* b_im    = (const float*)d_in[10];
    const float* c_re    = (const float*)d_in[11];
    const float* c_im    = (const float*)d_in[12];
    const float* dvec    = (const float*)d_in[13];
    const float* lstep   = (const float*)d_in[14];
    const float* out_w   = (const float*)d_in[15];
    const float* out_b   = (const float*)d_in[16];
    const float* out2_w  = (const float*)d_in[17];
    const float* out2_b  = (const float*)d_in[18];
    float* out = (float*)d_out;

    enc_kernel<<<L, H>>>(x, enc_w, enc_b);

    for (int l = 0; l < NL; l++) {
        ln_kernel<<<L, 256>>>(norm_w + l * H, norm_b + l * H);
        scan_fused_kernel<<<H, 512>>>(lam_re + l * H * NSTATE, lam_im + l * H * NSTATE,
                                      b_re + l * H * NSTATE,  b_im + l * H * NSTATE,
                                      c_re + l * H * NSTATE,  c_im + l * H * NSTATE,
                                      dvec + l * H, lstep + l * H);
        dim3 grid(H / BN, L / BM);
        gemm_kernel<<<grid, 128>>>(out_w + l * H * H, out_b + l * H,
                                   out2_w + l * H * H, out2_b + l * H);
    }

    dec_kernel<<<256, 256>>>(dec_w, dec_b, out);
}